// round 6
// baseline (speedup 1.0000x reference)
#include <cuda_runtime.h>
#include <cuda_bf16.h>
#include <cstdint>
#include <math.h>

// Problem constants
#define NROWS 2048
#define VDIM  50257
#define VPAD  50272   // bf16 row stride
#define H_S   2048
#define H_T   4096

// Scratch (static device allocations)
__device__ __nv_bfloat16 g_logits_s[(size_t)NROWS * VPAD];  // 206 MB
__device__ __nv_bfloat16 g_logits_t[(size_t)NROWS * VPAD];  // 206 MB
__device__ float g_lse[2 * NROWS];
__device__ float g_row_ce[NROWS];
__device__ float g_row_valid[NROWS];
__device__ float g_row_kls[NROWS];
__device__ float g_row_klt[NROWS];

// ---------------------------------------------------------------------------
// XOR swizzle: 128-byte logical rows (64 bf16), 16B chunks (validated layout).
// ---------------------------------------------------------------------------
__device__ __forceinline__ uint32_t swz(uint32_t row, uint32_t chunk) {
    return row * 128u + ((chunk ^ (row & 7u)) << 4);
}

// ---------------------------------------------------------------------------
// GEMM: C[n,v] = sum_h A[n,h]*B[v,h];  A,B fp32 in GMEM (bf16-representable),
// converted to bf16 on the fly.  CTA tile 128x128x64, 8 warps (2x4),
// m16n8k8 with explicit fragment LDS (validated vs SIMT).  Double-buffered
// smem; global fp32 loads register-staged to overlap with mma compute.
// Output: bf16 logits (matches reference bf16-einsum quantization).
// ---------------------------------------------------------------------------
__global__ __launch_bounds__(256) void gemm_f32in_kernel(
    const float* __restrict__ A,   // [NROWS, H] fp32
    const float* __restrict__ B,   // [VDIM, H]  fp32
    __nv_bfloat16* __restrict__ C, // [NROWS, VPAD] bf16
    int H)
{
    extern __shared__ char smem[];   // 2 stages x (A 16KB + B 16KB) = 64KB

    const int tid   = threadIdx.x;
    const int lane  = tid & 31;
    const int warp  = tid >> 5;
    const int warp_m = warp >> 2;   // 0..1
    const int warp_n = warp & 3;    // 0..3
    const int m0 = blockIdx.x * 128;
    const int v0 = blockIdx.y * 128;

    const uint32_t sbase = (uint32_t)__cvta_generic_to_shared(smem);

    float acc[4][4][4];
    #pragma unroll
    for (int i = 0; i < 4; i++)
        #pragma unroll
        for (int j = 0; j < 4; j++)
            #pragma unroll
            for (int k = 0; k < 4; k++) acc[i][j][k] = 0.f;

    const int ktiles = H >> 6;

    // Copy roles: each thread loads 8 float4 from A and 8 from B per k-tile.
    const int row0 = tid >> 2;      // 0..63  (also +64)
    const int f0   = tid & 3;       // float4 slot base within row

    size_t aoff0 = (size_t)(m0 + row0) * H;
    size_t aoff1 = (size_t)(m0 + row0 + 64) * H;
    int vr0 = v0 + row0;       if (vr0 > VDIM - 1) vr0 = VDIM - 1;
    int vr1 = v0 + row0 + 64;  if (vr1 > VDIM - 1) vr1 = VDIM - 1;
    size_t boff0 = (size_t)vr0 * H;
    size_t boff1 = (size_t)vr1 * H;

    float4 ra[8], rb[8];

    auto load_regs = [&](int kt) {
        const int k0 = kt * 64;
        #pragma unroll
        for (int j = 0; j < 4; j++) {
            const int c = (f0 + 4 * j) * 4;
            ra[j]     = *(const float4*)(A + aoff0 + k0 + c);
            ra[j + 4] = *(const float4*)(A + aoff1 + k0 + c);
            rb[j]     = *(const float4*)(B + boff0 + k0 + c);
            rb[j + 4] = *(const float4*)(B + boff1 + k0 + c);
        }
    };

    auto store_smem = [&](int st) {
        const uint32_t aB = sbase + st * 32768;
        const uint32_t bB = aB + 16384;
        #pragma unroll
        for (int j = 0; j < 8; j++) {
            const int f = f0 + 4 * (j & 3);          // float4 index 0..15
            const int chunk = f >> 1;
            const int half8 = (f & 1) * 8;
            const int r = row0 + (j >> 2) * 64;
            __nv_bfloat162 lo_a = __floats2bfloat162_rn(ra[j].x, ra[j].y);
            __nv_bfloat162 hi_a = __floats2bfloat162_rn(ra[j].z, ra[j].w);
            __nv_bfloat162 lo_b = __floats2bfloat162_rn(rb[j].x, rb[j].y);
            __nv_bfloat162 hi_b = __floats2bfloat162_rn(rb[j].z, rb[j].w);
            uint32_t ua = aB + swz(r, chunk) + half8;
            uint32_t ub = bB + swz(r, chunk) + half8;
            asm volatile("st.shared.v2.b32 [%0], {%1,%2};\n" ::
                "r"(ua), "r"(*(uint32_t*)&lo_a), "r"(*(uint32_t*)&hi_a));
            asm volatile("st.shared.v2.b32 [%0], {%1,%2};\n" ::
                "r"(ub), "r"(*(uint32_t*)&lo_b), "r"(*(uint32_t*)&hi_b));
        }
    };

    const int frow = lane >> 2;
    const int fcol4 = (lane & 3) * 4;

    load_regs(0);
    store_smem(0);

    for (int kt = 0; kt < ktiles; kt++) {
        __syncthreads();                       // stage kt visible
        if (kt + 1 < ktiles) load_regs(kt + 1);   // overlap with compute

        const int st = kt & 1;
        const uint32_t aBase = sbase + st * 32768;
        const uint32_t bBase = aBase + 16384;

        #pragma unroll
        for (int c = 0; c < 8; c++) {
            uint32_t a0[4], a1[4], b0[4];
            #pragma unroll
            for (int mf = 0; mf < 4; mf++) {
                uint32_t r0 = warp_m * 64 + mf * 16 + frow;
                a0[mf] = *(const uint32_t*)((char*)smem + (aBase - sbase) + swz(r0,     c) + fcol4);
                a1[mf] = *(const uint32_t*)((char*)smem + (aBase - sbase) + swz(r0 + 8, c) + fcol4);
            }
            #pragma unroll
            for (int nf = 0; nf < 4; nf++) {
                uint32_t rb_ = warp_n * 32 + nf * 8 + frow;
                b0[nf] = *(const uint32_t*)((char*)smem + (bBase - sbase) + swz(rb_, c) + fcol4);
            }
            #pragma unroll
            for (int mf = 0; mf < 4; mf++)
                #pragma unroll
                for (int nf = 0; nf < 4; nf++)
                    asm volatile(
                        "mma.sync.aligned.m16n8k8.row.col.f32.bf16.bf16.f32 "
                        "{%0,%1,%2,%3}, {%4,%5}, {%6}, {%0,%1,%2,%3};\n"
                        : "+f"(acc[mf][nf][0]), "+f"(acc[mf][nf][1]),
                          "+f"(acc[mf][nf][2]), "+f"(acc[mf][nf][3])
                        : "r"(a0[mf]), "r"(a1[mf]), "r"(b0[nf]));
        }
        if (kt + 1 < ktiles) store_smem((kt + 1) & 1);
    }

    // Epilogue: bf16 stores
    const int row_in = lane >> 2;
    const int col_in = (lane & 3) * 2;
    #pragma unroll
    for (int mf = 0; mf < 4; mf++) {
        #pragma unroll
        for (int nf = 0; nf < 4; nf++) {
            int n0 = m0 + warp_m * 64 + mf * 16 + row_in;
            int v  = v0 + warp_n * 32 + nf * 8 + col_in;
            __nv_bfloat16* r0 = C + (size_t)n0 * VPAD;
            __nv_bfloat16* r1 = C + (size_t)(n0 + 8) * VPAD;
            if (v + 1 < VDIM) {
                *(__nv_bfloat162*)(r0 + v) = __floats2bfloat162_rn(acc[mf][nf][0], acc[mf][nf][1]);
                *(__nv_bfloat162*)(r1 + v) = __floats2bfloat162_rn(acc[mf][nf][2], acc[mf][nf][3]);
            } else if (v < VDIM) {
                r0[v] = __float2bfloat16_rn(acc[mf][nf][0]);
                r1[v] = __float2bfloat16_rn(acc[mf][nf][2]);
            }
        }
    }
}

// ---------------------------------------------------------------------------
// Per-row online logsumexp.  grid (NROWS, 2): y=0 student, y=1 teacher.
// ---------------------------------------------------------------------------
__global__ __launch_bounds__(256) void reduce_lse_kernel() {
    const int n = blockIdx.x;
    const __nv_bfloat16* row =
        (blockIdx.y == 0 ? g_logits_s : g_logits_t) + (size_t)n * VPAD;

    float m = -INFINITY, s = 0.f;
    for (int v = threadIdx.x; v < VDIM; v += 256) {
        float x = __bfloat162float(row[v]);
        float nm = fmaxf(m, x);
        s = s * expf(m - nm) + expf(x - nm);
        m = nm;
    }
    __shared__ float sm[256], ss[256];
    sm[threadIdx.x] = m; ss[threadIdx.x] = s;
    __syncthreads();
    for (int off = 128; off > 0; off >>= 1) {
        if (threadIdx.x < off) {
            float m2 = sm[threadIdx.x + off], s2 = ss[threadIdx.x + off];
            float m1 = sm[threadIdx.x],       s1 = ss[threadIdx.x];
            float nm = fmaxf(m1, m2);
            ss[threadIdx.x] = s1 * expf(m1 - nm) + s2 * expf(m2 - nm);
            sm[threadIdx.x] = nm;
        }
        __syncthreads();
    }
    if (threadIdx.x == 0)
        g_lse[blockIdx.y * NROWS + n] = sm[0] + logf(ss[0]);
}

// ---------------------------------------------------------------------------
// Per-row JSD terms + CE.  One CTA per row; deterministic tree reduction.
// ---------------------------------------------------------------------------
__global__ __launch_bounds__(256) void rowloss_kernel(const int* __restrict__ target) {
    const int n = blockIdx.x;
    const __nv_bfloat16* rs = g_logits_s + (size_t)n * VPAD;
    const __nv_bfloat16* rt = g_logits_t + (size_t)n * VPAD;
    const float ls = g_lse[n];
    const float lt = g_lse[NROWS + n];

    float as = 0.f, at = 0.f;
    for (int v = threadIdx.x; v < VDIM; v += 256) {
        float slp = __bfloat162float(rs[v]) - ls;
        float tlp = __bfloat162float(rt[v]) - lt;
        float sp = expf(slp), tp = expf(tlp);
        float lm = logf(0.5f * sp + 0.5f * tp);   // BETA = 0.5
        as += sp * (slp - lm);
        at += tp * (tlp - lm);
    }
    __shared__ float sa[256], sb[256];
    sa[threadIdx.x] = as; sb[threadIdx.x] = at;
    __syncthreads();
    for (int off = 128; off > 0; off >>= 1) {
        if (threadIdx.x < off) {
            sa[threadIdx.x] += sa[threadIdx.x + off];
            sb[threadIdx.x] += sb[threadIdx.x + off];
        }
        __syncthreads();
    }
    if (threadIdx.x == 0) {
        g_row_kls[n] = sa[0];
        g_row_klt[n] = sb[0];
        int tg = target[n];
        bool valid = (tg != -100);
        int tgs = valid ? tg : 0;
        g_row_ce[n]    = valid ? (ls - __bfloat162float(rs[tgs])) : 0.f;
        g_row_valid[n] = valid ? 1.f : 0.f;
    }
}

// ---------------------------------------------------------------------------
// Final combine -> scalar loss (deterministic).
// ---------------------------------------------------------------------------
__global__ __launch_bounds__(256) void combine_kernel(float* __restrict__ out) {
    __shared__ float s0[256], s1[256], s2[256], s3[256];
    float a = 0.f, b = 0.f, c = 0.f, d = 0.f;
    for (int n = threadIdx.x; n < NROWS; n += 256) {
        a += g_row_ce[n];
        b += g_row_valid[n];
        c += g_row_kls[n];
        d += g_row_klt[n];
    }
    s0[threadIdx.x] = a; s1[threadIdx.x] = b; s2[threadIdx.x] = c; s3[threadIdx.x] = d;
    __syncthreads();
    for (int off = 128; off > 0; off >>= 1) {
        if (threadIdx.x < off) {
            s0[threadIdx.x] += s0[threadIdx.x + off];
            s1[threadIdx.x] += s1[threadIdx.x + off];
            s2[threadIdx.x] += s2[threadIdx.x + off];
            s3[threadIdx.x] += s3[threadIdx.x + off];
        }
        __syncthreads();
    }
    if (threadIdx.x == 0) {
        float hard = s0[0] / s1[0];
        float jsd  = (0.5f * s3[0] + 0.5f * s2[0]) / (float)NROWS;  // BETA=0.5
        out[0] = 0.5f * hard + 0.5f * jsd;
    }
}

// ---------------------------------------------------------------------------
// Launch.  Inputs are FLOAT32 (harness widens the bf16 reference arrays);
// identified by element count.
// ---------------------------------------------------------------------------
extern "C" void kernel_launch(void* const* d_in, const int* in_sizes, int n_in,
                              void* d_out, int out_size) {
    const float* student = nullptr;
    const float* W_s     = nullptr;
    const float* teacher = nullptr;
    const float* W_t     = nullptr;
    const int*   target  = nullptr;

    for (int i = 0; i < n_in; i++) {
        long sz = in_sizes[i];
        if      (sz == (long)NROWS * H_S)      student = (const float*)d_in[i];
        else if (sz == (long)VDIM  * H_S)      W_s     = (const float*)d_in[i];
        else if (sz == (long)NROWS * H_T)      teacher = (const float*)d_in[i];
        else if (sz == (long)VDIM  * H_T)      W_t     = (const float*)d_in[i];
        else if (sz == (long)NROWS)            target  = (const int*)d_in[i];
    }

    __nv_bfloat16* Cs = nullptr; __nv_bfloat16* Ct = nullptr;
    cudaGetSymbolAddress((void**)&Cs, g_logits_s);
    cudaGetSymbolAddress((void**)&Ct, g_logits_t);

    cudaFuncSetAttribute(gemm_f32in_kernel,
                         cudaFuncAttributeMaxDynamicSharedMemorySize, 65536);

    dim3 ggrid(16, (VDIM + 127) / 128);   // x = M tiles innermost -> L2 weight reuse
    gemm_f32in_kernel<<<ggrid, 256, 65536>>>(student, W_s, Cs, H_S);
    gemm_f32in_kernel<<<ggrid, 256, 65536>>>(teacher, W_t, Ct, H_T);
    reduce_lse_kernel<<<dim3(NROWS, 2), 256>>>();
    rowloss_kernel<<<NROWS, 256>>>(target);
    combine_kernel<<<1, 256>>>((float*)d_out);
}

// round 8
// speedup vs baseline: 2.3282x; 2.3282x over previous
#include <cuda_runtime.h>
#include <cuda_bf16.h>
#include <cstdint>
#include <math.h>

// Problem constants
#define NROWS 2048
#define VDIM  50257
#define VPAD  50272   // bf16 row stride
#define H_S   2048
#define H_T   4096

// Scratch (static device allocations)
__device__ __nv_bfloat16 g_logits_s[(size_t)NROWS * VPAD];  // 206 MB
__device__ __nv_bfloat16 g_logits_t[(size_t)NROWS * VPAD];  // 206 MB
__device__ __nv_bfloat16 g_Ws_bf[(size_t)VDIM * H_S];       // 206 MB
__device__ __nv_bfloat16 g_Wt_bf[(size_t)VDIM * H_T];       // 412 MB
__device__ __nv_bfloat16 g_as_bf[(size_t)NROWS * H_S];
__device__ __nv_bfloat16 g_at_bf[(size_t)NROWS * H_T];
__device__ float g_row_ce[NROWS];
__device__ float g_row_valid[NROWS];
__device__ float g_row_kls[NROWS];
__device__ float g_row_klt[NROWS];

// ---------------------------------------------------------------------------
// Helpers
// ---------------------------------------------------------------------------
__device__ __forceinline__ uint32_t swz(uint32_t row, uint32_t chunk) {
    // 128-byte logical rows (64 bf16), 16B chunks, XOR swizzle
    return row * 128u + ((chunk ^ (row & 7u)) << 4);
}
__device__ __forceinline__ void cp16(uint32_t saddr, const void* gaddr) {
    asm volatile("cp.async.cg.shared.global [%0], [%1], 16;\n"
                 :: "r"(saddr), "l"(gaddr) : "memory");
}

// ---------------------------------------------------------------------------
// fp32 -> bf16 conversion (inputs are fp32-widened bf16; lossless)
// ---------------------------------------------------------------------------
__global__ __launch_bounds__(256) void cvt_kernel(
    const float* __restrict__ src, __nv_bfloat16* __restrict__ dst, size_t n4)
{
    for (size_t i = (size_t)blockIdx.x * 256 + threadIdx.x; i < n4;
         i += (size_t)gridDim.x * 256) {
        float4 v = *(const float4*)(src + i * 4);
        __nv_bfloat162 lo = __floats2bfloat162_rn(v.x, v.y);
        __nv_bfloat162 hi = __floats2bfloat162_rn(v.z, v.w);
        *(uint2*)(dst + i * 4) = make_uint2(*(uint32_t*)&lo, *(uint32_t*)&hi);
    }
}

// ---------------------------------------------------------------------------
// GEMM: C[n,v] = sum_h A[n,h]*B[v,h]  (bf16 in, fp32 accum, bf16 out)
// CTA tile 128x128x64, 8 warps (2x4), warp tile 64x32.
// Double-buffered cp.async (wait_group 1), k16 mma + ldmatrix.
// (Round-1 core — fragment mapping validated; prior failures were input dtype.)
// ---------------------------------------------------------------------------
__global__ __launch_bounds__(256) void gemm_bf16_kernel(
    const __nv_bfloat16* __restrict__ A,   // [NROWS, H]
    const __nv_bfloat16* __restrict__ B,   // [VDIM, H]
    __nv_bfloat16* __restrict__ C,         // [NROWS, VPAD]
    int H)
{
    extern __shared__ char smem[];

    const int tid   = threadIdx.x;
    const int lane  = tid & 31;
    const int warp  = tid >> 5;
    const int warp_m = warp >> 2;   // 0..1
    const int warp_n = warp & 3;    // 0..3
    const int m0 = blockIdx.x * 128;
    const int v0 = blockIdx.y * 128;

    const uint32_t sA = (uint32_t)__cvta_generic_to_shared(smem);
    const uint32_t sB = sA + 32768;   // A: 2 x 16KB, B: 2 x 16KB

    float acc[4][4][4];
    #pragma unroll
    for (int i = 0; i < 4; i++)
        #pragma unroll
        for (int j = 0; j < 4; j++)
            #pragma unroll
            for (int k = 0; k < 4; k++) acc[i][j][k] = 0.f;

    const int ktiles = H >> 6;
    const int lr = tid >> 3;    // 0..31 (row group)
    const int lc = tid & 7;     // 16B chunk 0..7

    size_t aoff[4], boff[4];
    #pragma unroll
    for (int j = 0; j < 4; j++) {
        aoff[j] = (size_t)(m0 + lr + j * 32) * H;
        int vr = v0 + lr + j * 32;
        if (vr > VDIM - 1) vr = VDIM - 1;   // clamp; clamped rows never stored
        boff[j] = (size_t)vr * H;
    }

    // Prologue: stage 0
    #pragma unroll
    for (int j = 0; j < 4; j++) {
        cp16(sA + swz(lr + j * 32, lc), A + aoff[j] + lc * 8);
        cp16(sB + swz(lr + j * 32, lc), B + boff[j] + lc * 8);
    }
    asm volatile("cp.async.commit_group;\n" ::: "memory");

    for (int kt = 0; kt < ktiles; kt++) {
        if (kt + 1 < ktiles) {
            const int st = (kt + 1) & 1;
            const int kk0 = (kt + 1) * 64;
            #pragma unroll
            for (int j = 0; j < 4; j++) {
                cp16(sA + st * 16384 + swz(lr + j * 32, lc), A + aoff[j] + kk0 + lc * 8);
                cp16(sB + st * 16384 + swz(lr + j * 32, lc), B + boff[j] + kk0 + lc * 8);
            }
        }
        asm volatile("cp.async.commit_group;\n" ::: "memory");
        asm volatile("cp.async.wait_group 1;\n" ::: "memory");
        __syncthreads();

        const int st = kt & 1;
        const uint32_t aBase = sA + st * 16384;
        const uint32_t bBase = sB + st * 16384;

        #pragma unroll
        for (int kk = 0; kk < 4; kk++) {
            uint32_t a[4][4], b[4][2];
            #pragma unroll
            for (int mf = 0; mf < 4; mf++) {
                uint32_t row = warp_m * 64 + mf * 16 + (lane & 15);
                uint32_t chunk = kk * 2 + (lane >> 4);
                uint32_t addr = aBase + swz(row, chunk);
                asm volatile("ldmatrix.sync.aligned.m8n8.x4.shared.b16 {%0,%1,%2,%3}, [%4];\n"
                    : "=r"(a[mf][0]), "=r"(a[mf][1]), "=r"(a[mf][2]), "=r"(a[mf][3])
                    : "r"(addr));
            }
            #pragma unroll
            for (int nf = 0; nf < 4; nf++) {
                uint32_t row = warp_n * 32 + nf * 8 + (lane & 7);
                uint32_t chunk = kk * 2 + ((lane >> 3) & 1);
                uint32_t addr = bBase + swz(row, chunk);
                asm volatile("ldmatrix.sync.aligned.m8n8.x2.shared.b16 {%0,%1}, [%2];\n"
                    : "=r"(b[nf][0]), "=r"(b[nf][1]) : "r"(addr));
            }
            #pragma unroll
            for (int mf = 0; mf < 4; mf++)
                #pragma unroll
                for (int nf = 0; nf < 4; nf++)
                    asm volatile(
                        "mma.sync.aligned.m16n8k16.row.col.f32.bf16.bf16.f32 "
                        "{%0,%1,%2,%3}, {%4,%5,%6,%7}, {%8,%9}, {%0,%1,%2,%3};\n"
                        : "+f"(acc[mf][nf][0]), "+f"(acc[mf][nf][1]),
                          "+f"(acc[mf][nf][2]), "+f"(acc[mf][nf][3])
                        : "r"(a[mf][0]), "r"(a[mf][1]), "r"(a[mf][2]), "r"(a[mf][3]),
                          "r"(b[nf][0]), "r"(b[nf][1]));
        }
        __syncthreads();
    }

    // Epilogue: bf16 stores (matches reference bf16 quantization grid)
    const int row_in = lane >> 2;
    const int col_in = (lane & 3) * 2;
    #pragma unroll
    for (int mf = 0; mf < 4; mf++) {
        #pragma unroll
        for (int nf = 0; nf < 4; nf++) {
            int n0 = m0 + warp_m * 64 + mf * 16 + row_in;
            int v  = v0 + warp_n * 32 + nf * 8 + col_in;
            __nv_bfloat16* r0 = C + (size_t)n0 * VPAD;
            __nv_bfloat16* r1 = C + (size_t)(n0 + 8) * VPAD;
            if (v + 1 < VDIM) {
                *(__nv_bfloat162*)(r0 + v) = __floats2bfloat162_rn(acc[mf][nf][0], acc[mf][nf][1]);
                *(__nv_bfloat162*)(r1 + v) = __floats2bfloat162_rn(acc[mf][nf][2], acc[mf][nf][3]);
            } else if (v < VDIM) {
                r0[v] = __float2bfloat16_rn(acc[mf][nf][0]);
                r1[v] = __float2bfloat16_rn(acc[mf][nf][2]);
            }
        }
    }
}

// ---------------------------------------------------------------------------
// Fused per-row loss: pass 1 = online lse for student+teacher; pass 2 (L2-hot)
// = JSD terms + CE.  One CTA per row, 256 threads, fast-math exp/log.
// ---------------------------------------------------------------------------
#define NPAIR (VDIM / 2)   // 25128; tail element VDIM-1 by thread 0
__global__ __launch_bounds__(256) void rowloss_kernel(const int* __restrict__ target) {
    const int n = blockIdx.x;
    const __nv_bfloat16* rs = g_logits_s + (size_t)n * VPAD;
    const __nv_bfloat16* rt = g_logits_t + (size_t)n * VPAD;
    const __nv_bfloat162* rs2 = (const __nv_bfloat162*)rs;
    const __nv_bfloat162* rt2 = (const __nv_bfloat162*)rt;

    __shared__ float sh0[256], sh1[256], sh2[256], sh3[256];
    __shared__ float s_ls, s_lt;

    // ---- pass 1: online logsumexp for both rows ----
    float ms = -INFINITY, ss = 0.f, mt = -INFINITY, st = 0.f;
    for (int p = threadIdx.x; p < NPAIR; p += 256) {
        __nv_bfloat162 xs2 = rs2[p], xt2 = rt2[p];
        float s0 = __bfloat162float(xs2.x), s1 = __bfloat162float(xs2.y);
        float t0 = __bfloat162float(xt2.x), t1 = __bfloat162float(xt2.y);
        float nms = fmaxf(ms, fmaxf(s0, s1));
        ss = ss * __expf(ms - nms) + __expf(s0 - nms) + __expf(s1 - nms);
        ms = nms;
        float nmt = fmaxf(mt, fmaxf(t0, t1));
        st = st * __expf(mt - nmt) + __expf(t0 - nmt) + __expf(t1 - nmt);
        mt = nmt;
    }
    if (threadIdx.x == 0) {
        float s0 = __bfloat162float(rs[VDIM - 1]);
        float nms = fmaxf(ms, s0);
        ss = ss * __expf(ms - nms) + __expf(s0 - nms); ms = nms;
        float t0 = __bfloat162float(rt[VDIM - 1]);
        float nmt = fmaxf(mt, t0);
        st = st * __expf(mt - nmt) + __expf(t0 - nmt); mt = nmt;
    }
    sh0[threadIdx.x] = ms; sh1[threadIdx.x] = ss;
    sh2[threadIdx.x] = mt; sh3[threadIdx.x] = st;
    __syncthreads();
    for (int off = 128; off > 0; off >>= 1) {
        if (threadIdx.x < off) {
            float m2 = sh0[threadIdx.x + off], s2 = sh1[threadIdx.x + off];
            float m1 = sh0[threadIdx.x],       s1 = sh1[threadIdx.x];
            float nm = fmaxf(m1, m2);
            sh1[threadIdx.x] = s1 * __expf(m1 - nm) + s2 * __expf(m2 - nm);
            sh0[threadIdx.x] = nm;
            m2 = sh2[threadIdx.x + off]; s2 = sh3[threadIdx.x + off];
            m1 = sh2[threadIdx.x];       s1 = sh3[threadIdx.x];
            nm = fmaxf(m1, m2);
            sh3[threadIdx.x] = s1 * __expf(m1 - nm) + s2 * __expf(m2 - nm);
            sh2[threadIdx.x] = nm;
        }
        __syncthreads();
    }
    if (threadIdx.x == 0) {
        s_ls = sh0[0] + __logf(sh1[0]);
        s_lt = sh2[0] + __logf(sh3[0]);
    }
    __syncthreads();
    const float ls = s_ls, lt = s_lt;

    // ---- pass 2 (rows now L2/L1 resident): JSD terms ----
    float as = 0.f, at = 0.f;
    for (int p = threadIdx.x; p < NPAIR; p += 256) {
        __nv_bfloat162 s2v = rs2[p], t2v = rt2[p];
        #pragma unroll
        for (int h = 0; h < 2; h++) {
            float sv = __bfloat162float(h ? s2v.y : s2v.x);
            float tv = __bfloat162float(h ? t2v.y : t2v.x);
            float slp = sv - ls, tlp = tv - lt;
            float sp = __expf(slp), tp = __expf(tlp);
            float lm = __logf(0.5f * sp + 0.5f * tp);   // BETA = 0.5
            as += sp * (slp - lm);
            at += tp * (tlp - lm);
        }
    }
    if (threadIdx.x == 0) {
        float slp = __bfloat162float(rs[VDIM - 1]) - ls;
        float tlp = __bfloat162float(rt[VDIM - 1]) - lt;
        float sp = __expf(slp), tp = __expf(tlp);
        float lm = __logf(0.5f * sp + 0.5f * tp);
        as += sp * (slp - lm);
        at += tp * (tlp - lm);
    }
    sh0[threadIdx.x] = as; sh1[threadIdx.x] = at;
    __syncthreads();
    for (int off = 128; off > 0; off >>= 1) {
        if (threadIdx.x < off) {
            sh0[threadIdx.x] += sh0[threadIdx.x + off];
            sh1[threadIdx.x] += sh1[threadIdx.x + off];
        }
        __syncthreads();
    }
    if (threadIdx.x == 0) {
        g_row_kls[n] = sh0[0];
        g_row_klt[n] = sh1[0];
        int tg = target[n];
        bool valid = (tg != -100);
        int tgs = valid ? tg : 0;
        g_row_ce[n]    = valid ? (ls - __bfloat162float(rs[tgs])) : 0.f;
        g_row_valid[n] = valid ? 1.f : 0.f;
    }
}

// ---------------------------------------------------------------------------
// Final combine -> scalar loss (deterministic).
// ---------------------------------------------------------------------------
__global__ __launch_bounds__(256) void combine_kernel(float* __restrict__ out) {
    __shared__ float s0[256], s1[256], s2[256], s3[256];
    float a = 0.f, b = 0.f, c = 0.f, d = 0.f;
    for (int n = threadIdx.x; n < NROWS; n += 256) {
        a += g_row_ce[n];
        b += g_row_valid[n];
        c += g_row_kls[n];
        d += g_row_klt[n];
    }
    s0[threadIdx.x] = a; s1[threadIdx.x] = b; s2[threadIdx.x] = c; s3[threadIdx.x] = d;
    __syncthreads();
    for (int off = 128; off > 0; off >>= 1) {
        if (threadIdx.x < off) {
            s0[threadIdx.x] += s0[threadIdx.x + off];
            s1[threadIdx.x] += s1[threadIdx.x + off];
            s2[threadIdx.x] += s2[threadIdx.x + off];
            s3[threadIdx.x] += s3[threadIdx.x + off];
        }
        __syncthreads();
    }
    if (threadIdx.x == 0) {
        float hard = s0[0] / s1[0];
        float jsd  = (0.5f * s3[0] + 0.5f * s2[0]) / (float)NROWS;  // BETA=0.5
        out[0] = 0.5f * hard + 0.5f * jsd;
    }
}

// ---------------------------------------------------------------------------
// Launch.  Inputs are FLOAT32 (harness widens bf16); identified by size.
// ---------------------------------------------------------------------------
extern "C" void kernel_launch(void* const* d_in, const int* in_sizes, int n_in,
                              void* d_out, int out_size) {
    const float* student = nullptr;
    const float* W_s     = nullptr;
    const float* teacher = nullptr;
    const float* W_t     = nullptr;
    const int*   target  = nullptr;

    for (int i = 0; i < n_in; i++) {
        long sz = in_sizes[i];
        if      (sz == (long)NROWS * H_S)      student = (const float*)d_in[i];
        else if (sz == (long)VDIM  * H_S)      W_s     = (const float*)d_in[i];
        else if (sz == (long)NROWS * H_T)      teacher = (const float*)d_in[i];
        else if (sz == (long)VDIM  * H_T)      W_t     = (const float*)d_in[i];
        else if (sz == (long)NROWS)            target  = (const int*)d_in[i];
    }

    __nv_bfloat16 *Cs, *Ct, *Wsb, *Wtb, *asb, *atb;
    cudaGetSymbolAddress((void**)&Cs,  g_logits_s);
    cudaGetSymbolAddress((void**)&Ct,  g_logits_t);
    cudaGetSymbolAddress((void**)&Wsb, g_Ws_bf);
    cudaGetSymbolAddress((void**)&Wtb, g_Wt_bf);
    cudaGetSymbolAddress((void**)&asb, g_as_bf);
    cudaGetSymbolAddress((void**)&atb, g_at_bf);

    cudaFuncSetAttribute(gemm_bf16_kernel,
                         cudaFuncAttributeMaxDynamicSharedMemorySize, 65536);

    // fp32 -> bf16 (lossless: values are bf16-representable)
    cvt_kernel<<<4096, 256>>>(W_s,     Wsb, (size_t)VDIM  * H_S / 4);
    cvt_kernel<<<4096, 256>>>(W_t,     Wtb, (size_t)VDIM  * H_T / 4);
    cvt_kernel<<<512,  256>>>(student, asb, (size_t)NROWS * H_S / 4);
    cvt_kernel<<<512,  256>>>(teacher, atb, (size_t)NROWS * H_T / 4);

    dim3 ggrid(NROWS / 128, (VDIM + 127) / 128);   // (16, 393), M innermost
    gemm_bf16_kernel<<<ggrid, 256, 65536>>>(asb, Wsb, Cs, H_S);
    gemm_bf16_kernel<<<ggrid, 256, 65536>>>(atb, Wtb, Ct, H_T);

    rowloss_kernel<<<NROWS, 256>>>(target);
    combine_kernel<<<1, 256>>>((float*)d_out);
}